// round 14
// baseline (speedup 1.0000x reference)
#include <cuda_runtime.h>
#include <math.h>

// BackupBarrierCBF — closed-form per-corner argmin, delta-yaw form, warp-private
// staging. Grid shaped to 512x256 so oe*MLP_p1 < 16 (below the cross-CTA
// L1tex-queue contention threshold -> CTA spread at its 1.10 floor).
#define T_LO 1.0f
#define T_HI 50.0f

#define THREADS 256
#define ELEMS_PER_BLOCK 256
#define FLOATS_PER_WARP (32 * 15)     // 480 floats = 120 float4 per warp

__device__ __forceinline__ float tanh_approx(float x) {
    float y;
    asm("tanh.approx.f32 %0, %1;" : "=f"(y) : "f"(x));
    return y;
}

__global__ __launch_bounds__(THREADS)
void cbf_kernel(const float* __restrict__ data, float* __restrict__ out, int n) {
    __shared__ float sm[ELEMS_PER_BLOCK * 15];

    int e0   = blockIdx.x * ELEMS_PER_BLOCK;
    int warp = threadIdx.x >> 5;
    int lane = threadIdx.x & 31;

    // Warp-private staging: each warp loads its own 32 elements (1920 B,
    // 16B-aligned: 32*15*4). 120 float4 / 32 lanes -> 4 front-batched LDG.128
    // per lane. Only __syncwarp needed — warps fully independent.
    {
        const float4* g4 = (const float4*)(data + (size_t)(e0 + warp * 32) * 15);
        float4* s4 = (float4*)(sm + warp * FLOATS_PER_WARP);
        #pragma unroll
        for (int i = lane; i < FLOATS_PER_WARP / 4; i += 32)
            s4[i] = g4[i];
    }
    __syncwarp();

    const float* pp = sm + threadIdx.x * 15;   // stride 15: conflict-free
    float exg  = pp[0],  eyg  = pp[1],  eyaw = pp[2],  ev = pp[3];
    float axg  = pp[4],  ayg  = pp[5],  ayaw = pp[6],  av = pp[7];
    float eL   = pp[8],  eW   = pp[9];
    float aL   = pp[11], aW   = pp[12];
    float dt   = pp[14];

    float se, ce, sd, cd;
    __sincosf(eyaw, &se, &ce);
    __sincosf(ayaw - eyaw, &sd, &cd);    // delta yaw drives p,q and corner axes

    // Per-step relative velocity in the ego frame (closed form via dyaw).
    float p  = dt * fmaf(av, cd, -ev);
    float q  = dt * (av * sd);
    float ap = fabsf(p), aq = fabsf(q);
    float rp = __fdividef(1.0f, p);
    float rq = __fdividef(1.0f, q);
    float rs = __fdividef(1.0f, ap + aq);

    // Relative center at t=0 in the ego frame.
    float rx0 = axg - exg, ry0 = ayg - eyg;
    float Xc  =  rx0 * ce + ry0 * se;
    float Yc  = -rx0 * se + ry0 * ce;

    // Agent half-axes in the ego frame (rotation by dyaw).
    float hx = 0.5f * aL, hy = 0.5f * aW;
    float ux =  hx * cd, uy = hx * sd;
    float vx = -hy * sd, vy = hy * cd;

    const float kx  = 0.5f * eL + 1.0f;   // OFFSET_X
    const float ky  = 0.5f * eW + 0.3f;   // OFFSET_Y
    const float cdk = kx - ky;
    const float nkx = -kx, nky = -ky;

    float hacc[4];

    #pragma unroll
    for (int i = 0; i < 4; ++i) {
        float X = (i < 2) ? (Xc + ux) : (Xc - ux);
        float Y = (i < 2) ? (Yc + uy) : (Yc - uy);
        if (i & 1) { X -= vx; Y -= vy; } else { X += vx; Y += vy; }

        float t1 = -X * rp;                        // vertex of |X+pt|
        float t2 = -Y * rq;                        // vertex of |Y+qt|
        float g2t1 = fabsf(fmaf(q, t1, Y)) + nky;  // g2 at t1
        float g1t2 = fabsf(fmaf(p, t2, X)) + nkx;  // g1 at t2

        // Crossing of the two V-shapes between the vertices.
        // sign via copysign (LOP) instead of predicate+select.
        float csn  = copysignf(cdk, t2 - t1);
        float tint = fmaf(ap, t1, fmaf(aq, t2, csn)) * rs;

        // Closed-form continuous argmin (NaN comparisons fall through safely).
        float ts = (g2t1 <= nkx) ? t1 : ((g1t2 <= nky) ? t2 : tint);
        ts = fminf(fmaxf(ts, T_LO), T_HI);         // NaN -> T_LO

        float tf = floorf(ts);
        float te = fminf(tf + 1.0f, T_HI);
        float m0 = fmaxf(fabsf(fmaf(p, tf, X)) + nkx,
                         fabsf(fmaf(q, tf, Y)) + nky);
        float m1 = fmaxf(fabsf(fmaf(p, te, X)) + nkx,
                         fabsf(fmaf(q, te, Y)) + nky);
        hacc[i] = fminf(m0, m1);
    }

    float hm = fminf(fminf(hacc[0], hacc[1]), fminf(hacc[2], hacc[3]));

    // (sigmoid(h/5) - 0.5) * 10 == 5 * tanh(h/10)
    out[e0 + threadIdx.x] = 5.0f * tanh_approx(hm * 0.1f);
}

extern "C" void kernel_launch(void* const* d_in, const int* in_sizes, int n_in,
                              void* d_out, int out_size) {
    const float* data = (const float*)d_in[0];
    float* out = (float*)d_out;
    int n = out_size;                  // B*A = 131072, multiple of 256
    int blocks = (n + ELEMS_PER_BLOCK - 1) / ELEMS_PER_BLOCK;   // 512
    cbf_kernel<<<blocks, THREADS>>>(data, out, n);
}